// round 15
// baseline (speedup 1.0000x reference)
#include <cuda_runtime.h>

#define Bb     8
#define Nn     3136
#define Cc     64
#define CI     32
#define BNROWS 25088          // Bb * Nn
#define LAMF   0.1f
#define HSTEP  0.05f
#define BNEPS  1e-3f
#define INVN   (1.0f / 3136.0f)

// ---- scratch (static device globals; no allocation) ----
__device__ float d_theta[BNROWS * CI];
__device__ float d_phi[BNROWS * CI];
__device__ float d_phisum[Bb * CI];      // published by k_apply<0> chunk-0 blocks
__device__ float d_pspart[392 * CI];     // per-front-block phi-sum partials
__device__ float d_M[2][Bb * 2048];      // REDG accum; scrubbed stream-ordered:
                                         //  d_M[1] zeroed by apply<0>, d_M[0] by reduceM1
__device__ float d_g1[BNROWS * Cc];

__device__ __forceinline__ void redg_v4(float* p, float a, float b, float c, float d) {
    asm volatile("red.global.add.v4.f32 [%0], {%1, %2, %3, %4};"
                 :: "l"(p), "f"(a), "f"(b), "f"(c), "f"(d) : "memory");
}
__device__ __forceinline__ unsigned tf32(float x) {
    unsigned r; asm("cvt.rna.tf32.f32 %0, %1;" : "=r"(r) : "f"(x)); return r;
}
__device__ __forceinline__ float tf32f(float x) {       // tf32 bits as float
    return __uint_as_float(tf32(x));
}
__device__ __forceinline__ float4 tf32f4(float4 v) {
    return make_float4(tf32f(v.x), tf32f(v.y), tf32f(v.z), tf32f(v.w));
}
__device__ __forceinline__ unsigned fb(float x) { return __float_as_uint(x); }
__device__ __forceinline__ void mma_tf32(float4& d,
        unsigned a0, unsigned a1, unsigned a2, unsigned a3,
        unsigned b0, unsigned b1) {
    asm("mma.sync.aligned.m16n8k8.row.col.f32.tf32.tf32.f32 "
        "{%0,%1,%2,%3}, {%4,%5,%6,%7}, {%8,%9}, {%0,%1,%2,%3};"
        : "+f"(d.x), "+f"(d.y), "+f"(d.z), "+f"(d.w)
        : "r"(a0), "r"(a1), "r"(a2), "r"(a3), "r"(b0), "r"(b1));
}

// ===========================================================================
// K1 (front): 64 rows/block, grid 392.
//   theta/phi = x @ Wt/Wp + bias  (scalar GEMM, warp = 8 rows, lane = d)
//   + per-block phisum partial; fused M0 partial = phi^T x (tf32 MMA + v4 REDG)
// sph stored pre-converted to tf32 (feeds only the MMA).
__global__ void __launch_bounds__(256) k_front(
        const float* __restrict__ x,
        const float* __restrict__ Wt, const float* __restrict__ bt,
        const float* __restrict__ Wp, const float* __restrict__ bp) {
    __shared__ float sm[11040];
    float* sx   = sm;            // x [row 64][c 64] pad 68   (4352) fp32
    float* sWt  = sm + 4352;     // Wt^T [d 32][k 64] pad 68  (2176)
    float* sWp  = sm + 6528;     // Wp^T [d 32][k 64] pad 68  (2176)
    float* sph  = sm + 8704;     // phi [row 64][d 32] pad 36 (2304) tf32 bits
    float* sp   = sm + 11008;    // 32
    float* part = sm + 4352;     // overlay: M0 partial [d 32][c 64] pad 68 (2176)

    int t  = threadIdx.x;
    int gb = blockIdx.x;
    int b  = gb / 49;
    int r0 = gb * 64;

    {
        const float4* xg = (const float4*)(x + r0 * 64);
#pragma unroll
        for (int j = 0; j < 4; j++) {
            int e = t + j * 256;
            int r = e >> 4, c4 = (e & 15) * 4;
            *(float4*)(sx + r * 68 + c4) = xg[e];
        }
    }
    for (int e = t; e < 2048; e += 256) {
        int k = e >> 5, d = e & 31;
        sWt[d * 68 + k] = Wt[e];
        sWp[d * 68 + k] = Wp[e];
    }
    if (t < 32) sp[t] = 0.f;
    __syncthreads();

    int w = t >> 5, d = t & 31;
    float th[8], ph[8];
    float bt_d = bt[d], bp_d = bp[d];
#pragma unroll
    for (int j = 0; j < 8; j++) { th[j] = bt_d; ph[j] = bp_d; }

    const float* xr = sx + w * 8 * 68;
    const float* wt = sWt + d * 68;
    const float* wp = sWp + d * 68;
#pragma unroll 8
    for (int k = 0; k < 64; k += 4) {
        float4 a = *(const float4*)(wt + k);
        float4 b2 = *(const float4*)(wp + k);
#pragma unroll
        for (int j = 0; j < 8; j++) {
            float4 xv = *(const float4*)(xr + j * 68 + k);
            th[j] = fmaf(xv.x, a.x, th[j]);  th[j] = fmaf(xv.y, a.y, th[j]);
            th[j] = fmaf(xv.z, a.z, th[j]);  th[j] = fmaf(xv.w, a.w, th[j]);
            ph[j] = fmaf(xv.x, b2.x, ph[j]); ph[j] = fmaf(xv.y, b2.y, ph[j]);
            ph[j] = fmaf(xv.z, b2.z, ph[j]); ph[j] = fmaf(xv.w, b2.w, ph[j]);
        }
    }
    int r = r0 + w * 8;
    float phs = 0.f;
#pragma unroll
    for (int j = 0; j < 8; j++) {
        d_theta[(r + j) * 32 + d] = th[j];
        d_phi[(r + j) * 32 + d]   = ph[j];
        sph[(w * 8 + j) * 36 + d] = tf32f(ph[j]);   // pre-converted
        phs += ph[j];
    }
    atomicAdd(&sp[d], phs);
    __syncthreads();
    if (t < 32) d_pspart[gb * 32 + t] = sp[t];

    // fused M0 partial (A = phi^T tf32-staged, B = x converted on load)
    int lane = t & 31;
    int gq = lane >> 2, tg = lane & 3;
    int db = (w & 1) * 16;
    int ct = (w >> 1) * 8;

    float4 c0 = make_float4(0.f, 0.f, 0.f, 0.f);
    float4 c1v = make_float4(0.f, 0.f, 0.f, 0.f);
#pragma unroll
    for (int kb = 0; kb < 64; kb += 8) {
        unsigned a0 = fb(sph[(kb + tg) * 36 + db + gq]);
        unsigned a1 = fb(sph[(kb + tg) * 36 + db + gq + 8]);
        unsigned a2 = fb(sph[(kb + tg + 4) * 36 + db + gq]);
        unsigned a3 = fb(sph[(kb + tg + 4) * 36 + db + gq + 8]);
        unsigned b0 = tf32(sx[(kb + tg) * 68 + ct + gq]);
        unsigned b1 = tf32(sx[(kb + tg + 4) * 68 + ct + gq]);
        mma_tf32(c0, a0, a1, a2, a3, b0, b1);
        unsigned b2 = tf32(sx[(kb + tg) * 68 + ct + 32 + gq]);
        unsigned b3 = tf32(sx[(kb + tg + 4) * 68 + ct + 32 + gq]);
        mma_tf32(c1v, a0, a1, a2, a3, b2, b3);
    }
    __syncthreads();

    {
        int cA = ct + tg * 2;
        *(float2*)(part + (db + gq) * 68 + cA)          = make_float2(c0.x, c0.y);
        *(float2*)(part + (db + gq + 8) * 68 + cA)      = make_float2(c0.z, c0.w);
        *(float2*)(part + (db + gq) * 68 + cA + 32)     = make_float2(c1v.x, c1v.y);
        *(float2*)(part + (db + gq + 8) * 68 + cA + 32) = make_float2(c1v.z, c1v.w);
    }
    __syncthreads();

    int dd = t >> 3, cc = (t & 7) * 8;
    const float* p0 = part + dd * 68 + cc;
    float4 e0 = *(const float4*)(p0);
    float4 e1 = *(const float4*)(p0 + 4);
    float* Mb = d_M[0] + b * 2048 + dd * 64 + cc;
    redg_v4(Mb,     e0.x, e0.y, e0.z, e0.w);
    redg_v4(Mb + 4, e1.x, e1.y, e1.z, e1.w);
}

// ===========================================================================
// K3 (reduceM1): M[1][b] += phi[b]^T @ g1[b], tf32 MMA, staged pre-converted.
// Blocks 0-15 also zero d_M[0] (stream-ordered scrub for next replay).
__global__ void __launch_bounds__(256) k_reduceM1() {
    __shared__ float sm[6656];
    float* sph  = sm;          // phi [row 64][d 32] pad 36  (2304) tf32
    float* sg   = sm + 2304;   // g1  [row 64][c 64] pad 68  (4352) tf32
    float* part = sm;          // overlay: [d 32][c 64] pad 68 (2176)

    int t     = threadIdx.x;
    int b     = blockIdx.x / 49;
    int chunk = blockIdx.x % 49;
    int row0  = b * Nn + chunk * 64;

    if (blockIdx.x < 16)
        ((float4*)d_M[0])[blockIdx.x * 256 + t] = make_float4(0.f, 0.f, 0.f, 0.f);

    {
        const float4* phg = (const float4*)(d_phi + row0 * 32);
        const float4* gg  = (const float4*)(d_g1 + row0 * 64);
#pragma unroll
        for (int j = 0; j < 2; j++) {
            int e = t + j * 256;
            int r = e >> 3, d4 = (e & 7) * 4;
            *(float4*)(sph + r * 36 + d4) = tf32f4(phg[e]);
        }
#pragma unroll
        for (int j = 0; j < 4; j++) {
            int e = t + j * 256;
            int r = e >> 4, c4 = (e & 15) * 4;
            *(float4*)(sg + r * 68 + c4) = tf32f4(gg[e]);
        }
    }
    __syncthreads();

    int w = t >> 5, lane = t & 31;
    int gq = lane >> 2, tg = lane & 3;
    int db = (w & 1) * 16;
    int ct = (w >> 1) * 8;

    float4 c0 = make_float4(0.f, 0.f, 0.f, 0.f);
    float4 c1v = make_float4(0.f, 0.f, 0.f, 0.f);
#pragma unroll
    for (int kb = 0; kb < 64; kb += 8) {
        unsigned a0 = fb(sph[(kb + tg) * 36 + db + gq]);
        unsigned a1 = fb(sph[(kb + tg) * 36 + db + gq + 8]);
        unsigned a2 = fb(sph[(kb + tg + 4) * 36 + db + gq]);
        unsigned a3 = fb(sph[(kb + tg + 4) * 36 + db + gq + 8]);
        unsigned b0 = fb(sg[(kb + tg) * 68 + ct + gq]);
        unsigned b1 = fb(sg[(kb + tg + 4) * 68 + ct + gq]);
        mma_tf32(c0, a0, a1, a2, a3, b0, b1);
        unsigned b2 = fb(sg[(kb + tg) * 68 + ct + 32 + gq]);
        unsigned b3 = fb(sg[(kb + tg + 4) * 68 + ct + 32 + gq]);
        mma_tf32(c1v, a0, a1, a2, a3, b2, b3);
    }
    __syncthreads();

    {
        int cA = ct + tg * 2;
        *(float2*)(part + (db + gq) * 68 + cA)          = make_float2(c0.x, c0.y);
        *(float2*)(part + (db + gq + 8) * 68 + cA)      = make_float2(c0.z, c0.w);
        *(float2*)(part + (db + gq) * 68 + cA + 32)     = make_float2(c1v.x, c1v.y);
        *(float2*)(part + (db + gq + 8) * 68 + cA + 32) = make_float2(c1v.z, c1v.w);
    }
    __syncthreads();

    int dd = t >> 3, cc = (t & 7) * 8;
    const float* p0 = part + dd * 68 + cc;
    float4 e0 = *(const float4*)(p0);
    float4 e1 = *(const float4*)(p0 + 4);
    float* Mb = d_M[1] + b * 2048 + dd * 64 + cc;
    redg_v4(Mb,     e0.x, e0.y, e0.z, e0.w);
    redg_v4(Mb + 4, e1.x, e1.y, e1.z, e1.w);
}

// ===========================================================================
// K2/K4 (apply): 32 rows/block, grid 784 (occupancy), tf32 pre-converted smem.
//   phase1: raw = theta @ M (K=32); fg = (lam/N)*raw - (s/N)*g
//   phase2: o = fg @ W (K=64); bias+BN+ReLU; out = x + 0.05*o
// 8 warps = 2 row bands x 4 col-16 groups (2 n8 tiles each).
// ITER==0: phisum reduced in-block from d_pspart (chunk-0 publishes),
//          blocks 0-15 scrub d_M[1]. ITER==1: phisum from d_phisum.
template<int ITER>
__global__ void __launch_bounds__(256) k_apply(
        const float* __restrict__ x,
        const float* __restrict__ Wst, const float* __restrict__ bst,
        const float* __restrict__ gam, const float* __restrict__ bet,
        const float* __restrict__ mmean, const float* __restrict__ mvar,
        float* __restrict__ out_ext) {
    const float* gin = ITER ? d_g1 : x;
    float* out       = ITER ? out_ext : d_g1;

    __shared__ float sm[8256];
    float* sTh  = sm;           // theta [row 32][d 32] pad 36  (1152) tf32
    float* sM   = sm + 1152;    // M [k 32][c 64] pad 68         (2176) tf32
    float* sW   = sm + 3328;    // W [k 64][c 64] pad 68         (4352) tf32
    float* sFg  = sm;           // overlay (over sTh+sM): fg [row 32][k 64] pad 68 (2176)
    float* sP   = sm + 7680;    // params (256)
    float* ss   = sm + 7936;    // 32
    float* sps  = sm + 7968;    // 32
    float* sred = sm + 8000;    // 256

    int t  = threadIdx.x;
    int r0 = blockIdx.x * 32;
    int b  = blockIdx.x / 98;
    int chunk = blockIdx.x % 98;

    if (ITER == 0 && blockIdx.x < 16)
        ((float4*)d_M[1])[blockIdx.x * 256 + t] = make_float4(0.f, 0.f, 0.f, 0.f);

    // stage theta [row][d] pad 36, tf32
    {
        const float4* thg = (const float4*)(d_theta + r0 * 32);
        int e = t;                      // 256 f4
        int r = e >> 3, d4 = (e & 7) * 4;
        *(float4*)(sTh + r * 36 + d4) = tf32f4(thg[e]);
    }
    // stage M [k][c] pad 68, tf32
    const float* Mi = d_M[ITER] + b * 2048;
#pragma unroll
    for (int j = 0; j < 2; j++) {
        int e = t + j * 256;
        int k = e >> 4, c4 = (e & 15) * 4;
        *(float4*)(sM + k * 68 + c4) = tf32f4(((const float4*)Mi)[e]);
    }
    // stage W [k][c] pad 68, tf32
    const float* Wi = Wst + ITER * 4096;
#pragma unroll
    for (int j = 0; j < 4; j++) {
        int e = t + j * 256;
        int k = e >> 4, c4 = (e & 15) * 4;
        *(float4*)(sW + k * 68 + c4) = tf32f4(((const float4*)Wi)[e]);
    }
    if (t < 64) {
        int ic = ITER * 64 + t;
        sP[t]       = gam[ic] * rsqrtf(mvar[ic] + BNEPS);
        sP[64 + t]  = bst[ic];
        sP[128 + t] = mmean[ic];
        sP[192 + t] = bet[ic];
    }
    if (ITER == 0) {
        int lane = t & 31, grp = t >> 5;
        float a = 0.f;
        for (int j = grp; j < 49; j += 8)
            a += d_pspart[(b * 49 + j) * 32 + lane];
        sred[grp * 32 + lane] = a;
    } else {
        if (t < 32) sps[t] = d_phisum[b * 32 + t];
    }
    __syncthreads();
    if (ITER == 0) {
        if (t < 32) {
            float a = 0.f;
#pragma unroll
            for (int g2 = 0; g2 < 8; g2++) a += sred[g2 * 32 + t];
            sps[t] = a;
            if (chunk == 0) d_phisum[b * 32 + t] = a;
        }
        __syncthreads();
    }

    if (t < 32) {   // -(s/N) per row (tf32-rounded theta; error << budget)
        float a = 0.f;
#pragma unroll
        for (int k = 0; k < 32; k++) a = fmaf(sTh[t * 36 + k], sps[k], a);
        ss[t] = a * (-LAMF * INVN);
    }
    __syncthreads();

    int w = t >> 5, lane = t & 31;
    int gq = lane >> 2, tg = lane & 3;
    int rb = (w >> 2) * 16;        // 2 row bands
    int ch = (w & 3) * 16;         // 4 col groups, 2 n8 tiles each
    int row0l = rb + gq, row1l = rb + gq + 8;

    // ---- phase 1: raw = theta @ M (K=32) ----
    float4 c[2];
    c[0] = make_float4(0.f, 0.f, 0.f, 0.f);
    c[1] = make_float4(0.f, 0.f, 0.f, 0.f);
#pragma unroll
    for (int kb = 0; kb < 32; kb += 8) {
        unsigned a0 = fb(sTh[row0l * 36 + kb + tg]);
        unsigned a1 = fb(sTh[row1l * 36 + kb + tg]);
        unsigned a2 = fb(sTh[row0l * 36 + kb + tg + 4]);
        unsigned a3 = fb(sTh[row1l * 36 + kb + tg + 4]);
#pragma unroll
        for (int nt = 0; nt < 2; nt++) {
            int cb = ch + nt * 8;
            unsigned b0 = fb(sM[(kb + tg) * 68 + cb + gq]);
            unsigned b1 = fb(sM[(kb + tg + 4) * 68 + cb + gq]);
            mma_tf32(c[nt], a0, a1, a2, a3, b0, b1);
        }
    }
    {
        const float c1f = LAMF * INVN;
        float sn0 = ss[row0l], sn1 = ss[row1l];
#pragma unroll
        for (int nt = 0; nt < 2; nt++) {
            int cb2 = ch + nt * 8 + tg * 2;
            float2 g0 = *(const float2*)(gin + (r0 + row0l) * 64 + cb2);
            float2 g1 = *(const float2*)(gin + (r0 + row1l) * 64 + cb2);
            c[nt].x = fmaf(sn0, g0.x, c1f * c[nt].x);
            c[nt].y = fmaf(sn0, g0.y, c1f * c[nt].y);
            c[nt].z = fmaf(sn1, g1.x, c1f * c[nt].z);
            c[nt].w = fmaf(sn1, g1.y, c1f * c[nt].w);
        }
    }
    __syncthreads();   // sTh/sM fragment reads done; overlay sFg

    // fg [row][k] pad 68, tf32 pre-converted for phase 2
#pragma unroll
    for (int nt = 0; nt < 2; nt++) {
        int cb2 = ch + nt * 8 + tg * 2;
        *(float2*)(sFg + row0l * 68 + cb2) = make_float2(tf32f(c[nt].x), tf32f(c[nt].y));
        *(float2*)(sFg + row1l * 68 + cb2) = make_float2(tf32f(c[nt].z), tf32f(c[nt].w));
    }
    __syncthreads();

    // ---- phase 2: o = fg @ W (K=64) ----
    float4 o[2];
    o[0] = make_float4(0.f, 0.f, 0.f, 0.f);
    o[1] = make_float4(0.f, 0.f, 0.f, 0.f);
#pragma unroll
    for (int kb = 0; kb < 64; kb += 8) {
        unsigned a0 = fb(sFg[row0l * 68 + kb + tg]);
        unsigned a1 = fb(sFg[row1l * 68 + kb + tg]);
        unsigned a2 = fb(sFg[row0l * 68 + kb + tg + 4]);
        unsigned a3 = fb(sFg[row1l * 68 + kb + tg + 4]);
#pragma unroll
        for (int nt = 0; nt < 2; nt++) {
            int cb = ch + nt * 8;
            unsigned b0 = fb(sW[(kb + tg) * 68 + cb + gq]);
            unsigned b1 = fb(sW[(kb + tg + 4) * 68 + cb + gq]);
            mma_tf32(o[nt], a0, a1, a2, a3, b0, b1);
        }
    }

    // epilogue
    int gr0 = r0 + row0l, gr1 = r0 + row1l;
#pragma unroll
    for (int nt = 0; nt < 2; nt++) {
        int cb2 = ch + nt * 8 + tg * 2;
        float scl0 = sP[cb2],       scl1 = sP[cb2 + 1];
        float bi0  = sP[64 + cb2],  bi1  = sP[64 + cb2 + 1];
        float mn0  = sP[128 + cb2], mn1  = sP[128 + cb2 + 1];
        float be0  = sP[192 + cb2], be1  = sP[192 + cb2 + 1];
        float2 x0 = *(const float2*)(x + gr0 * 64 + cb2);
        float2 x1 = *(const float2*)(x + gr1 * 64 + cb2);
        float o00 = fmaxf((o[nt].x + bi0 - mn0) * scl0 + be0, 0.f);
        float o01 = fmaxf((o[nt].y + bi1 - mn1) * scl1 + be1, 0.f);
        float o10 = fmaxf((o[nt].z + bi0 - mn0) * scl0 + be0, 0.f);
        float o11 = fmaxf((o[nt].w + bi1 - mn1) * scl1 + be1, 0.f);
        *(float2*)(out + gr0 * 64 + cb2) =
            make_float2(x0.x + HSTEP * o00, x0.y + HSTEP * o01);
        *(float2*)(out + gr1 * 64 + cb2) =
            make_float2(x1.x + HSTEP * o10, x1.y + HSTEP * o11);
    }
}

// ---------------------------------------------------------------------------
extern "C" void kernel_launch(void* const* d_in, const int* in_sizes, int n_in,
                              void* d_out, int out_size) {
    const float* x     = (const float*)d_in[0];
    const float* Wt    = (const float*)d_in[1];
    const float* bt    = (const float*)d_in[2];
    const float* Wp    = (const float*)d_in[3];
    const float* bp    = (const float*)d_in[4];
    const float* Wst   = (const float*)d_in[5];
    const float* bst   = (const float*)d_in[6];
    const float* gam   = (const float*)d_in[7];
    const float* bet   = (const float*)d_in[8];
    const float* mmean = (const float*)d_in[9];
    const float* mvar  = (const float*)d_in[10];
    float* out = (float*)d_out;

    k_front<<<Bb * 49, 256>>>(x, Wt, bt, Wp, bp);
    k_apply<0><<<BNROWS / 32, 256>>>(x, Wst, bst, gam, bet, mmean, mvar, out);
    k_reduceM1<<<Bb * 49, 256>>>();
    k_apply<1><<<BNROWS / 32, 256>>>(x, Wst, bst, gam, bet, mmean, mvar, out);
}

// round 17
// speedup vs baseline: 1.0556x; 1.0556x over previous
#include <cuda_runtime.h>

#define Bb     8
#define Nn     3136
#define Cc     64
#define CI     32
#define BNROWS 25088          // Bb * Nn
#define LAMF   0.1f
#define HSTEP  0.05f
#define BNEPS  1e-3f
#define INVN   (1.0f / 3136.0f)

// ---- scratch (static device globals; no allocation) ----
__device__ float d_theta[BNROWS * CI];
__device__ float d_phi[BNROWS * CI];
__device__ float d_phisum[Bb * CI];      // published by k_apply<0> chunk-0 blocks
__device__ float d_pspart[392 * CI];     // per-front-block phi-sum partials
__device__ float d_M[2][Bb * 2048];      // REDG accum; scrubbed stream-ordered:
                                         //  d_M[1] zeroed by apply<0>, d_M[0] by reduceM1
__device__ float d_g1[BNROWS * Cc];

__device__ __forceinline__ void redg_v4(float* p, float a, float b, float c, float d) {
    asm volatile("red.global.add.v4.f32 [%0], {%1, %2, %3, %4};"
                 :: "l"(p), "f"(a), "f"(b), "f"(c), "f"(d) : "memory");
}
__device__ __forceinline__ unsigned tf32(float x) {
    unsigned r; asm("cvt.rna.tf32.f32 %0, %1;" : "=r"(r) : "f"(x)); return r;
}
__device__ __forceinline__ void mma_tf32(float4& d,
        unsigned a0, unsigned a1, unsigned a2, unsigned a3,
        unsigned b0, unsigned b1) {
    asm("mma.sync.aligned.m16n8k8.row.col.f32.tf32.tf32.f32 "
        "{%0,%1,%2,%3}, {%4,%5,%6,%7}, {%8,%9}, {%0,%1,%2,%3};"
        : "+f"(d.x), "+f"(d.y), "+f"(d.z), "+f"(d.w)
        : "r"(a0), "r"(a1), "r"(a2), "r"(a3), "r"(b0), "r"(b1));
}

// ===========================================================================
// K1 (front): 64 rows/block, grid 392. (R14 exact)
__global__ void __launch_bounds__(256) k_front(
        const float* __restrict__ x,
        const float* __restrict__ Wt, const float* __restrict__ bt,
        const float* __restrict__ Wp, const float* __restrict__ bp) {
    __shared__ float sm[11040];
    float* sx   = sm;            // x [row 64][c 64] pad 68   (4352)
    float* sWt  = sm + 4352;     // Wt^T [d 32][k 64] pad 68  (2176)
    float* sWp  = sm + 6528;     // Wp^T [d 32][k 64] pad 68  (2176)
    float* sph  = sm + 8704;     // phi [row 64][d 32] pad 36 (2304)
    float* sp   = sm + 11008;    // 32
    float* part = sm + 4352;     // overlay: M0 partial [d 32][c 64] pad 68

    int t  = threadIdx.x;
    int gb = blockIdx.x;
    int b  = gb / 49;
    int r0 = gb * 64;

    {
        const float4* xg = (const float4*)(x + r0 * 64);
#pragma unroll
        for (int j = 0; j < 4; j++) {
            int e = t + j * 256;
            int r = e >> 4, c4 = (e & 15) * 4;
            *(float4*)(sx + r * 68 + c4) = xg[e];
        }
    }
    for (int e = t; e < 2048; e += 256) {
        int k = e >> 5, d = e & 31;
        sWt[d * 68 + k] = Wt[e];
        sWp[d * 68 + k] = Wp[e];
    }
    if (t < 32) sp[t] = 0.f;
    __syncthreads();

    int w = t >> 5, d = t & 31;
    float th[8], ph[8];
    float bt_d = bt[d], bp_d = bp[d];
#pragma unroll
    for (int j = 0; j < 8; j++) { th[j] = bt_d; ph[j] = bp_d; }

    const float* xr = sx + w * 8 * 68;
    const float* wt = sWt + d * 68;
    const float* wp = sWp + d * 68;
#pragma unroll 8
    for (int k = 0; k < 64; k += 4) {
        float4 a = *(const float4*)(wt + k);
        float4 b2 = *(const float4*)(wp + k);
#pragma unroll
        for (int j = 0; j < 8; j++) {
            float4 xv = *(const float4*)(xr + j * 68 + k);
            th[j] = fmaf(xv.x, a.x, th[j]);  th[j] = fmaf(xv.y, a.y, th[j]);
            th[j] = fmaf(xv.z, a.z, th[j]);  th[j] = fmaf(xv.w, a.w, th[j]);
            ph[j] = fmaf(xv.x, b2.x, ph[j]); ph[j] = fmaf(xv.y, b2.y, ph[j]);
            ph[j] = fmaf(xv.z, b2.z, ph[j]); ph[j] = fmaf(xv.w, b2.w, ph[j]);
        }
    }
    int r = r0 + w * 8;
    float phs = 0.f;
#pragma unroll
    for (int j = 0; j < 8; j++) {
        d_theta[(r + j) * 32 + d] = th[j];
        d_phi[(r + j) * 32 + d]   = ph[j];
        sph[(w * 8 + j) * 36 + d] = ph[j];
        phs += ph[j];
    }
    atomicAdd(&sp[d], phs);
    __syncthreads();
    if (t < 32) d_pspart[gb * 32 + t] = sp[t];

    int lane = t & 31;
    int gq = lane >> 2, tg = lane & 3;
    int db = (w & 1) * 16;
    int ct = (w >> 1) * 8;

    float4 c0 = make_float4(0.f, 0.f, 0.f, 0.f);
    float4 c1v = make_float4(0.f, 0.f, 0.f, 0.f);
#pragma unroll
    for (int kb = 0; kb < 64; kb += 8) {
        unsigned a0 = tf32(sph[(kb + tg) * 36 + db + gq]);
        unsigned a1 = tf32(sph[(kb + tg) * 36 + db + gq + 8]);
        unsigned a2 = tf32(sph[(kb + tg + 4) * 36 + db + gq]);
        unsigned a3 = tf32(sph[(kb + tg + 4) * 36 + db + gq + 8]);
        unsigned b0 = tf32(sx[(kb + tg) * 68 + ct + gq]);
        unsigned b1 = tf32(sx[(kb + tg + 4) * 68 + ct + gq]);
        mma_tf32(c0, a0, a1, a2, a3, b0, b1);
        unsigned b2 = tf32(sx[(kb + tg) * 68 + ct + 32 + gq]);
        unsigned b3 = tf32(sx[(kb + tg + 4) * 68 + ct + 32 + gq]);
        mma_tf32(c1v, a0, a1, a2, a3, b2, b3);
    }
    __syncthreads();

    {
        int cA = ct + tg * 2;
        *(float2*)(part + (db + gq) * 68 + cA)          = make_float2(c0.x, c0.y);
        *(float2*)(part + (db + gq + 8) * 68 + cA)      = make_float2(c0.z, c0.w);
        *(float2*)(part + (db + gq) * 68 + cA + 32)     = make_float2(c1v.x, c1v.y);
        *(float2*)(part + (db + gq + 8) * 68 + cA + 32) = make_float2(c1v.z, c1v.w);
    }
    __syncthreads();

    int dd = t >> 3, cc = (t & 7) * 8;
    const float* p0 = part + dd * 68 + cc;
    float4 e0 = *(const float4*)(p0);
    float4 e1 = *(const float4*)(p0 + 4);
    float* Mb = d_M[0] + b * 2048 + dd * 64 + cc;
    redg_v4(Mb,     e0.x, e0.y, e0.z, e0.w);
    redg_v4(Mb + 4, e1.x, e1.y, e1.z, e1.w);
}

// ===========================================================================
// K3 (reduceM1): M[1][b] += phi[b]^T @ g1[b] via tf32 MMA. (R14 exact)
__global__ void __launch_bounds__(256) k_reduceM1() {
    __shared__ float sm[6656];
    float* sph  = sm;          // phi [row 64][d 32] pad 36  (2304)
    float* sg   = sm + 2304;   // g1  [row 64][c 64] pad 68  (4352)
    float* part = sm;          // overlay: [d 32][c 64] pad 68 (2176)

    int t     = threadIdx.x;
    int b     = blockIdx.x / 49;
    int chunk = blockIdx.x % 49;
    int row0  = b * Nn + chunk * 64;

    if (blockIdx.x < 16)
        ((float4*)d_M[0])[blockIdx.x * 256 + t] = make_float4(0.f, 0.f, 0.f, 0.f);

    {
        const float4* phg = (const float4*)(d_phi + row0 * 32);
        const float4* gg  = (const float4*)(d_g1 + row0 * 64);
#pragma unroll
        for (int j = 0; j < 2; j++) {
            int e = t + j * 256;
            int r = e >> 3, d4 = (e & 7) * 4;
            *(float4*)(sph + r * 36 + d4) = phg[e];
        }
#pragma unroll
        for (int j = 0; j < 4; j++) {
            int e = t + j * 256;
            int r = e >> 4, c4 = (e & 15) * 4;
            *(float4*)(sg + r * 68 + c4) = gg[e];
        }
    }
    __syncthreads();

    int w = t >> 5, lane = t & 31;
    int gq = lane >> 2, tg = lane & 3;
    int db = (w & 1) * 16;
    int ct = (w >> 1) * 8;

    float4 c0 = make_float4(0.f, 0.f, 0.f, 0.f);
    float4 c1v = make_float4(0.f, 0.f, 0.f, 0.f);
#pragma unroll
    for (int kb = 0; kb < 64; kb += 8) {
        unsigned a0 = tf32(sph[(kb + tg) * 36 + db + gq]);
        unsigned a1 = tf32(sph[(kb + tg) * 36 + db + gq + 8]);
        unsigned a2 = tf32(sph[(kb + tg + 4) * 36 + db + gq]);
        unsigned a3 = tf32(sph[(kb + tg + 4) * 36 + db + gq + 8]);
        unsigned b0 = tf32(sg[(kb + tg) * 68 + ct + gq]);
        unsigned b1 = tf32(sg[(kb + tg + 4) * 68 + ct + gq]);
        mma_tf32(c0, a0, a1, a2, a3, b0, b1);
        unsigned b2 = tf32(sg[(kb + tg) * 68 + ct + 32 + gq]);
        unsigned b3 = tf32(sg[(kb + tg + 4) * 68 + ct + 32 + gq]);
        mma_tf32(c1v, a0, a1, a2, a3, b2, b3);
    }
    __syncthreads();

    {
        int cA = ct + tg * 2;
        *(float2*)(part + (db + gq) * 68 + cA)          = make_float2(c0.x, c0.y);
        *(float2*)(part + (db + gq + 8) * 68 + cA)      = make_float2(c0.z, c0.w);
        *(float2*)(part + (db + gq) * 68 + cA + 32)     = make_float2(c1v.x, c1v.y);
        *(float2*)(part + (db + gq + 8) * 68 + cA + 32) = make_float2(c1v.z, c1v.w);
    }
    __syncthreads();

    int dd = t >> 3, cc = (t & 7) * 8;
    const float* p0 = part + dd * 68 + cc;
    float4 e0 = *(const float4*)(p0);
    float4 e1 = *(const float4*)(p0 + 4);
    float* Mb = d_M[1] + b * 2048 + dd * 64 + cc;
    redg_v4(Mb,     e0.x, e0.y, e0.z, e0.w);
    redg_v4(Mb + 4, e1.x, e1.y, e1.z, e1.w);
}

// ===========================================================================
// K2/K4 (apply): 64 rows/block, 512 THREADS (16 warps), grid 392.
// Same tile/staging as R14; warps = 4 row bands x 4 col groups (2 n8 tiles).
template<int ITER>
__global__ void __launch_bounds__(512) k_apply(
        const float* __restrict__ x,
        const float* __restrict__ Wst, const float* __restrict__ bst,
        const float* __restrict__ gam, const float* __restrict__ bet,
        const float* __restrict__ mmean, const float* __restrict__ mvar,
        float* __restrict__ out_ext) {
    const float* gin = ITER ? d_g1 : x;
    float* out       = ITER ? out_ext : d_g1;

    __shared__ float sm[9696];
    float* sTh  = sm;           // theta [row 64][d 32] pad 36   (2304)
    float* sM   = sm + 2304;    // M [k 32][c 64] pad 68          (2176)
    float* sW   = sm + 4480;    // W [k 64][c 64] pad 68          (4352)
    float* sFg  = sm;           // overlay: fg [row 64][k 64] pad 68 (4352)
    float* sP   = sm + 8832;    // params (256)
    float* ss   = sm + 9088;    // 64
    float* sps  = sm + 9152;    // 32
    float* sred = sm + 9184;    // 512 (ITER==0 phisum reduce, 16 groups)

    int t  = threadIdx.x;
    int r0 = blockIdx.x * 64;
    int b  = blockIdx.x / 49;
    int chunk = blockIdx.x % 49;

    if (ITER == 0 && blockIdx.x < 8)   // scrub d_M[1] (4096 f4 = 8 blocks x 512)
        ((float4*)d_M[1])[blockIdx.x * 512 + t] = make_float4(0.f, 0.f, 0.f, 0.f);

    // stage theta [row][d] pad 36  (512 f4)
    {
        const float4* thg = (const float4*)(d_theta + r0 * 32);
        int r = t >> 3, d4 = (t & 7) * 4;
        *(float4*)(sTh + r * 36 + d4) = thg[t];
    }
    // stage M [k][c] pad 68  (512 f4)
    {
        const float* Mi = d_M[ITER] + b * 2048;
        int k = t >> 4, c4 = (t & 15) * 4;
        *(float4*)(sM + k * 68 + c4) = ((const float4*)Mi)[t];
    }
    // stage W [k][c] pad 68  (1024 f4)
    const float* Wi = Wst + ITER * 4096;
#pragma unroll
    for (int j = 0; j < 2; j++) {
        int e = t + j * 512;
        int k = e >> 4, c4 = (e & 15) * 4;
        *(float4*)(sW + k * 68 + c4) = ((const float4*)Wi)[e];
    }
    // BN params
    if (t < 64) {
        int ic = ITER * 64 + t;
        sP[t]       = gam[ic] * rsqrtf(mvar[ic] + BNEPS);
        sP[64 + t]  = bst[ic];
        sP[128 + t] = mmean[ic];
        sP[192 + t] = bet[ic];
    }
    // phisum
    if (ITER == 0) {
        int lane = t & 31, grp = t >> 5;    // 16 groups
        float a = 0.f;
        for (int j = grp; j < 49; j += 16)
            a += d_pspart[(b * 49 + j) * 32 + lane];
        sred[grp * 32 + lane] = a;
    } else {
        if (t < 32) sps[t] = d_phisum[b * 32 + t];
    }
    __syncthreads();
    if (ITER == 0) {
        if (t < 32) {
            float a = 0.f;
#pragma unroll
            for (int g2 = 0; g2 < 16; g2++) a += sred[g2 * 32 + t];
            sps[t] = a;
            if (chunk == 0) d_phisum[b * 32 + t] = a;   // publish for apply<1>
        }
        __syncthreads();
    }

    if (t < 64) {   // -(s/N) per row
        float a = 0.f;
#pragma unroll
        for (int k = 0; k < 32; k++) a = fmaf(sTh[t * 36 + k], sps[k], a);
        ss[t] = a * (-LAMF * INVN);
    }
    __syncthreads();

    int w = t >> 5, lane = t & 31;
    int gq = lane >> 2, tg = lane & 3;
    int rb = (w >> 2) * 16;        // 4 row bands
    int ch = (w & 3) * 16;         // 4 col groups, 2 n8 tiles each
    int row0l = rb + gq, row1l = rb + gq + 8;

    // ---- phase 1: raw = theta @ M (K=32) ----
    float4 c[2];
    c[0] = make_float4(0.f, 0.f, 0.f, 0.f);
    c[1] = make_float4(0.f, 0.f, 0.f, 0.f);
#pragma unroll
    for (int kb = 0; kb < 32; kb += 8) {
        unsigned a0 = tf32(sTh[row0l * 36 + kb + tg]);
        unsigned a1 = tf32(sTh[row1l * 36 + kb + tg]);
        unsigned a2 = tf32(sTh[row0l * 36 + kb + tg + 4]);
        unsigned a3 = tf32(sTh[row1l * 36 + kb + tg + 4]);
#pragma unroll
        for (int nt = 0; nt < 2; nt++) {
            int cb = ch + nt * 8;
            unsigned b0 = tf32(sM[(kb + tg) * 68 + cb + gq]);
            unsigned b1 = tf32(sM[(kb + tg + 4) * 68 + cb + gq]);
            mma_tf32(c[nt], a0, a1, a2, a3, b0, b1);
        }
    }
    {
        const float c1f = LAMF * INVN;
        float sn0 = ss[row0l], sn1 = ss[row1l];
#pragma unroll
        for (int nt = 0; nt < 2; nt++) {
            int cb2 = ch + nt * 8 + tg * 2;
            float2 g0 = *(const float2*)(gin + (r0 + row0l) * 64 + cb2);
            float2 g1 = *(const float2*)(gin + (r0 + row1l) * 64 + cb2);
            c[nt].x = fmaf(sn0, g0.x, c1f * c[nt].x);
            c[nt].y = fmaf(sn0, g0.y, c1f * c[nt].y);
            c[nt].z = fmaf(sn1, g1.x, c1f * c[nt].z);
            c[nt].w = fmaf(sn1, g1.y, c1f * c[nt].w);
        }
    }
    __syncthreads();   // sTh/sM fragment reads done; overlay sFg

    // fg [row][k] pad 68
#pragma unroll
    for (int nt = 0; nt < 2; nt++) {
        int cb2 = ch + nt * 8 + tg * 2;
        *(float2*)(sFg + row0l * 68 + cb2) = make_float2(c[nt].x, c[nt].y);
        *(float2*)(sFg + row1l * 68 + cb2) = make_float2(c[nt].z, c[nt].w);
    }
    __syncthreads();

    // ---- phase 2: o = fg @ W (K=64) ----
    float4 o[2];
    o[0] = make_float4(0.f, 0.f, 0.f, 0.f);
    o[1] = make_float4(0.f, 0.f, 0.f, 0.f);
#pragma unroll
    for (int kb = 0; kb < 64; kb += 8) {
        unsigned a0 = tf32(sFg[row0l * 68 + kb + tg]);
        unsigned a1 = tf32(sFg[row1l * 68 + kb + tg]);
        unsigned a2 = tf32(sFg[row0l * 68 + kb + tg + 4]);
        unsigned a3 = tf32(sFg[row1l * 68 + kb + tg + 4]);
#pragma unroll
        for (int nt = 0; nt < 2; nt++) {
            int cb = ch + nt * 8;
            unsigned b0 = tf32(sW[(kb + tg) * 68 + cb + gq]);
            unsigned b1 = tf32(sW[(kb + tg + 4) * 68 + cb + gq]);
            mma_tf32(o[nt], a0, a1, a2, a3, b0, b1);
        }
    }

    // epilogue
    int gr0 = r0 + row0l, gr1 = r0 + row1l;
#pragma unroll
    for (int nt = 0; nt < 2; nt++) {
        int cb2 = ch + nt * 8 + tg * 2;
        float scl0 = sP[cb2],       scl1 = sP[cb2 + 1];
        float bi0  = sP[64 + cb2],  bi1  = sP[64 + cb2 + 1];
        float mn0  = sP[128 + cb2], mn1  = sP[128 + cb2 + 1];
        float be0  = sP[192 + cb2], be1  = sP[192 + cb2 + 1];
        float2 x0 = *(const float2*)(x + gr0 * 64 + cb2);
        float2 x1 = *(const float2*)(x + gr1 * 64 + cb2);
        float o00 = fmaxf((o[nt].x + bi0 - mn0) * scl0 + be0, 0.f);
        float o01 = fmaxf((o[nt].y + bi1 - mn1) * scl1 + be1, 0.f);
        float o10 = fmaxf((o[nt].z + bi0 - mn0) * scl0 + be0, 0.f);
        float o11 = fmaxf((o[nt].w + bi1 - mn1) * scl1 + be1, 0.f);
        *(float2*)(out + gr0 * 64 + cb2) =
            make_float2(x0.x + HSTEP * o00, x0.y + HSTEP * o01);
        *(float2*)(out + gr1 * 64 + cb2) =
            make_float2(x1.x + HSTEP * o10, x1.y + HSTEP * o11);
    }
}

// ---------------------------------------------------------------------------
extern "C" void kernel_launch(void* const* d_in, const int* in_sizes, int n_in,
                              void* d_out, int out_size) {
    const float* x     = (const float*)d_in[0];
    const float* Wt    = (const float*)d_in[1];
    const float* bt    = (const float*)d_in[2];
    const float* Wp    = (const float*)d_in[3];
    const float* bp    = (const float*)d_in[4];
    const float* Wst   = (const float*)d_in[5];
    const float* bst   = (const float*)d_in[6];
    const float* gam   = (const float*)d_in[7];
    const float* bet   = (const float*)d_in[8];
    const float* mmean = (const float*)d_in[9];
    const float* mvar  = (const float*)d_in[10];
    float* out = (float*)d_out;

    k_front<<<Bb * 49, 256>>>(x, Wt, bt, Wp, bp);
    k_apply<0><<<BNROWS / 64, 512>>>(x, Wst, bst, gam, bet, mmean, mvar, out);
    k_reduceM1<<<Bb * 49, 256>>>();
    k_apply<1><<<BNROWS / 64, 512>>>(x, Wst, bst, gam, bet, mmean, mvar, out);
}